// round 17
// baseline (speedup 1.0000x reference)
#include <cuda_runtime.h>
#include <cuda_bf16.h>
#include <cuda_fp16.h>
#include <cstdint>
#include <cstring>

#define BN 2
#define CIN 64
#define HH 256
#define WW 256
#define KK 9
#define OC1 10
#define HW (HH*WW)

// ---------------- scratch ----------------
__device__ float g_off[BN*OC1*HW];
__device__ float g_offpart[BN*256*20];    // per-conv1-block (sum,sumsq) x 10 ch
__device__ float g_offstats[BN*5*2];
__device__ __align__(16) __half g_wh[KK*4096];         // [k][swizzled 64co x 64ci] fp16 (dsc conv)
__device__ __align__(16) __half g_wc1[KK*1024];        // [k][swizzled 16co x 64ci] fp16 (offset conv)
__device__ __align__(16) __half g_xh[(size_t)BN*HW*64]; // NHWC fp16: [b][y][x][ci]
__device__ float g_part[BN*512*16*2];
__device__ float g_outmr[BN*16*2];

// ---------------- mma helpers (baseline PTX, no 'a' features) ----------------
__device__ __forceinline__ uint32_t smem_u32(const void* p) {
    uint32_t a;
    asm("{ .reg .u64 t; cvta.to.shared.u64 t, %1; cvt.u32.u64 %0, t; }" : "=r"(a) : "l"(p));
    return a;
}
__device__ __forceinline__ void ldsm_x4(uint32_t* r, uint32_t addr) {
    asm volatile("ldmatrix.sync.aligned.m8n8.x4.shared.b16 {%0,%1,%2,%3}, [%4];"
                 : "=r"(r[0]), "=r"(r[1]), "=r"(r[2]), "=r"(r[3]) : "r"(addr));
}
__device__ __forceinline__ void ldsm_x2(uint32_t* r, uint32_t addr) {
    asm volatile("ldmatrix.sync.aligned.m8n8.x2.shared.b16 {%0,%1}, [%2];"
                 : "=r"(r[0]), "=r"(r[1]) : "r"(addr));
}
__device__ __forceinline__ void mma16816h(float* d, const uint32_t* a, const uint32_t* b) {
    asm volatile("mma.sync.aligned.m16n8k16.row.col.f32.f16.f16.f32 "
                 "{%0,%1,%2,%3}, {%4,%5,%6,%7}, {%8,%9}, {%0,%1,%2,%3};"
                 : "+f"(d[0]), "+f"(d[1]), "+f"(d[2]), "+f"(d[3])
                 : "r"(a[0]), "r"(a[1]), "r"(a[2]), "r"(a[3]), "r"(b[0]), "r"(b[1]));
}
__device__ __forceinline__ void cpasync16(uint32_t saddr, const void* gptr) {
    asm volatile("cp.async.ca.shared.global [%0], [%1], 16;" :: "r"(saddr), "l"(gptr) : "memory");
}

// smem layout for main_kernel (dynamic), 2 stages
#define OFF_SH(st)  ((st)*16384)            // [128 pix][64 ci] fp16 swizzled
#define OFF_WH(st)  (32768 + (st)*8192)     // [64 co][64 ci] fp16 swizzled
#define OFF_IY   49152                       // 9*128 floats
#define OFF_SUMS 53760                       // 32 floats
#define SMEM_BYTES 53888

// smem layout for conv1g (dynamic): 4 S tiles of 130 pixel-rows + 9 W tiles
#define C1S(i)   ((i)*16640)                // [130 pix][64 ci] fp16 swizzled, i=0..3
#define C1W(k)   (66560 + (k)*2048)         // [16 co][64 ci] fp16 swizzled
#define C1_SMEM  84992

// ---------------- kernel 1: x NCHW fp32 -> NHWC fp16 (smem transpose) ----------------
__global__ void xprep_kernel(const float* __restrict__ x) {
    int y = blockIdx.x, b = blockIdx.y;
    int t = threadIdx.x;
    __shared__ __half xs[256*66];
    const float* xb = x + (size_t)b*CIN*HW;
#pragma unroll 4
    for (int ci = 0; ci < 64; ci++) {
        float v = __ldg(xb + ((size_t)ci*HH + y)*WW + t);
        xs[t*66 + ci] = __float2half(v);
    }
    __syncthreads();
    char* dst = (char*)(g_xh + ((size_t)b*HW + (size_t)y*WW)*64);
#pragma unroll
    for (int j = 0; j < 8; j++) {
        int c = t + 256*j;
        int w = c >> 3, cig = c & 7;
        const uint32_t* src = (const uint32_t*)&xs[w*66];   // 4B-aligned
        uint4 v;
        v.x = src[cig*4 + 0];
        v.y = src[cig*4 + 1];
        v.z = src[cig*4 + 2];
        v.w = src[cig*4 + 3];
        *(uint4*)(dst + (size_t)c*16) = v;
    }
}

// ---------------- kernel 2a: w_dsc -> fp16, [k][64co][64ci] swizzled ----------------
__global__ void wprep_kernel(const float* __restrict__ wdsc) {
    int lin = blockIdx.x*256 + threadIdx.x;       // 9*64*64
    if (lin >= KK*64*64) return;
    int ci = lin & 63, co = (lin >> 6) & 63, k = lin >> 12;
    float v = wdsc[((size_t)(co*64 + ci))*KK + k];
    uint32_t off = (uint32_t)(co*128 + ci*2);
    uint32_t sw = off ^ ((off >> 3) & 0x70);
    *(__half*)((char*)g_wh + (size_t)k*8192 + sw) = __float2half(v);
}

// ---------------- kernel 2b: w_off -> fp16, [k][16co][64ci] swizzled (co>=10 zero) ----------------
__global__ void wprepc1_kernel(const float* __restrict__ woff) {
    int lin = blockIdx.x*256 + threadIdx.x;       // 9*16*64
    if (lin >= KK*16*64) return;
    int ci = lin & 63, co = (lin >> 6) & 15, k = lin >> 10;
    float v = (co < OC1) ? woff[((size_t)(co*64 + ci))*9 + k] : 0.f;
    uint32_t off = (uint32_t)(co*128 + ci*2);
    uint32_t sw = off ^ ((off >> 3) & 0x70);
    *(__half*)((char*)g_wc1 + (size_t)k*2048 + sw) = __float2half(v);
}

// ---------------- kernel 3: 3x3 offset conv via mma, 2 output rows per CTA ----------------
__global__ void __launch_bounds__(256, 2)
conv1g_kernel(const float* __restrict__ b_off) {
    extern __shared__ __align__(16) char smem[];
    __shared__ float sums20[20];
    uint32_t sb = smem_u32(smem);

    int t = threadIdx.x, lane = t & 31, wid = t >> 5;
    int b = blockIdx.z, h0 = blockIdx.y * 2, w0 = blockIdx.x * 128;
    if (t < 20) sums20[t] = 0.f;

    const char* xhb = (const char*)(g_xh + (size_t)b*HW*64);

    // copy all 9 W tiles (contiguous 18432 B, swizzle preserved)
    for (int i = t; i < 1152; i += 256)
        ((uint4*)(smem + C1W(0)))[i] = ((const uint4*)g_wc1)[i];

    // load 4 S tiles of 130 pixel rows (y = h0-1 .. h0+2)
    {
        int r = t >> 3, cig = t & 7;
#pragma unroll
        for (int ty = 0; ty < 4; ty++) {
            int y = h0 + ty - 1;
            bool yok = (y >= 0 && y < HH);
#pragma unroll
            for (int g = 0; g < 5; g++) {
                int row = r + g*32;
                if (row >= 130) break;
                int pix = w0 - 1 + row;
                uint4 v = make_uint4(0u, 0u, 0u, 0u);
                if (yok && pix >= 0 && pix < WW) {
                    uint32_t o = (((uint32_t)y << 8) + (uint32_t)pix) << 7;
                    v = __ldg((const uint4*)(xhb + o + (cig << 4)));
                }
                uint32_t off = (uint32_t)(row*128 + (cig << 4));
                uint32_t sw = off ^ ((off >> 3) & 0x70);
                *(uint4*)(smem + C1S(ty) + sw) = v;
            }
        }
    }
    __syncthreads();

    float acc[2][2][4];   // [row][nt][frag]
#pragma unroll
    for (int r = 0; r < 2; r++)
#pragma unroll
        for (int i = 0; i < 2; i++)
#pragma unroll
            for (int j = 0; j < 4; j++) acc[r][i][j] = 0.f;

#pragma unroll 1
    for (int k = 0; k < KK; k++) {
        int dy = k / 3, dxm = k % 3;
        uint32_t woff = C1W(k);
#pragma unroll
        for (int kt = 0; kt < 4; kt++) {
            uint32_t af[4];
            {
                uint32_t row = (uint32_t)(lane & 15);
                uint32_t c16 = (uint32_t)(kt*2 + (lane >> 4));
                uint32_t off = row*128 + c16*16;
                uint32_t sw = off ^ ((off >> 3) & 0x70);
                ldsm_x4(af, sb + woff + sw);
            }
#pragma unroll
            for (int r = 0; r < 2; r++) {
                int y = h0 + r + dy - 1;
                if (y < 0 || y >= HH) continue;   // zero-padding: exact skip
                uint32_t soff = C1S(r + dy);
#pragma unroll
                for (int nt = 0; nt < 2; nt++) {
                    uint32_t bf[2];
                    uint32_t row = (uint32_t)(wid*16 + nt*8 + (lane & 7) + dxm);
                    uint32_t c16 = (uint32_t)(kt*2 + ((lane >> 3) & 1));
                    uint32_t off = row*128 + c16*16;
                    uint32_t sw = off ^ ((off >> 3) & 0x70);
                    ldsm_x2(bf, sb + soff + sw);
                    mma16816h(acc[r][nt], af, bf);
                }
            }
        }
    }

    // epilogue: bias, store g_off (co<10), GN partials (both rows)
    {
        int q = lane >> 2;
        int pp = (lane & 3) * 2;
        float b0 = (q < OC1) ? __ldg(b_off + q) : 0.f;
        float b1 = (q + 8 < OC1) ? __ldg(b_off + q + 8) : 0.f;
        float s0 = 0.f, q0 = 0.f, s1 = 0.f, q1 = 0.f;
#pragma unroll
        for (int r = 0; r < 2; r++) {
            int h = h0 + r;
#pragma unroll
            for (int nt = 0; nt < 2; nt++) {
                int pix = wid*16 + nt*8 + pp;
                float v0 = acc[r][nt][0] + b0;
                float v1 = acc[r][nt][1] + b0;
                float v2 = acc[r][nt][2] + b1;
                float v3 = acc[r][nt][3] + b1;
                if (q < OC1) {
                    *(float2*)&g_off[((size_t)(b*OC1 + q)*HH + h)*WW + w0 + pix] = make_float2(v0, v1);
                    s0 += v0 + v1; q0 += v0*v0 + v1*v1;
                }
                if (q + 8 < OC1) {
                    *(float2*)&g_off[((size_t)(b*OC1 + q + 8)*HH + h)*WW + w0 + pix] = make_float2(v2, v3);
                    s1 += v2 + v3; q1 += v2*v2 + v3*v3;
                }
            }
        }
#pragma unroll
        for (int m = 1; m <= 2; m <<= 1) {
            s0 += __shfl_xor_sync(0xffffffff, s0, m);
            q0 += __shfl_xor_sync(0xffffffff, q0, m);
            s1 += __shfl_xor_sync(0xffffffff, s1, m);
            q1 += __shfl_xor_sync(0xffffffff, q1, m);
        }
        if ((lane & 3) == 0) {
            if (q < OC1)     { atomicAdd(&sums20[q*2], s0);       atomicAdd(&sums20[q*2+1], q0); }
            if (q + 8 < OC1) { atomicAdd(&sums20[(q+8)*2], s1);   atomicAdd(&sums20[(q+8)*2+1], q1); }
        }
    }
    __syncthreads();
    if (t < 20) {
        int blk = blockIdx.x + 2*blockIdx.y;    // 0..255
        g_offpart[((size_t)(b*256) + blk)*20 + t] = sums20[t];
    }
}

// ---------------- kernel 4: reduce offset GN partials ----------------
__global__ void offstats_kernel() {
    int b = blockIdx.x / 5, g = blockIdx.x % 5;
    int t = threadIdx.x;
    float s = 0.f, q = 0.f;
    if (t < 256) {
        const float* p = g_offpart + ((size_t)(b*256) + t)*20;
        s = p[(2*g)*2]   + p[(2*g+1)*2];
        q = p[(2*g)*2+1] + p[(2*g+1)*2+1];
    }
    __shared__ float rs[256], rq[256];
    rs[t] = s; rq[t] = q; __syncthreads();
    for (int o = 128; o > 0; o >>= 1) {
        if (t < o) { rs[t] += rs[t+o]; rq[t] += rq[t+o]; }
        __syncthreads();
    }
    if (t == 0) {
        float n = (float)(2*HW);
        float mean = rs[0] / n;
        float var = rq[0] / n - mean*mean;
        g_offstats[(b*5+g)*2]   = mean;
        g_offstats[(b*5+g)*2+1] = rsqrtf(var + 1e-5f);
    }
}

// ---------------- kernel 5: pipelined coords + NHWC sampling + fp16 mma.sync GEMM ----------------
// Gather for chunk g+1 issued one full iteration before its convert/store.
__global__ void __launch_bounds__(256, 3)
main_kernel(const float* __restrict__ x,
            const float* __restrict__ gno_w, const float* __restrict__ gno_b,
            const float* __restrict__ b_dsc,
            float* __restrict__ out) {
    extern __shared__ __align__(16) char smem[];
    uint32_t sb = smem_u32(smem);
    float* iy_sh = (float*)(smem + OFF_IY);
    float* sums  = (float*)(smem + OFF_SUMS);

    int t = threadIdx.x, lane = t & 31, wid = t >> 5;
    int b = blockIdx.z, h = blockIdx.y, w0 = blockIdx.x * 128;
    if (t < 32) sums[t] = 0.f;

    // Phase 0: GN+tanh, outward cumsum, clamped iy for 128 pixels x 9 taps
    if (t < 128) {
        int p = t, wg = w0 + p;
        float v[9];
#pragma unroll
        for (int c = 0; c < 9; c++) {
            float raw = g_off[((size_t)(b*OC1 + c)*HH + h)*WW + wg];
            int g = c >> 1;
            float mean = g_offstats[(b*5+g)*2];
            float rstd = g_offstats[(b*5+g)*2+1];
            v[c] = tanhf((raw - mean)*rstd*gno_w[c] + gno_b[c]);
        }
        float cum[9];
        cum[4] = 0.f;
        cum[3] = v[3]; cum[2] = cum[3]+v[2]; cum[1] = cum[2]+v[1]; cum[0] = cum[1]+v[0];
        cum[5] = v[5]; cum[6] = cum[5]+v[6]; cum[7] = cum[6]+v[7]; cum[8] = cum[7]+v[8];
#pragma unroll
        for (int k = 0; k < 9; k++)
            iy_sh[k*128 + p] = fminf(fmaxf((float)h + cum[k], 0.f), 255.f);
    }

    const char* xhb = (const char*)(g_xh + (size_t)b*HW*64);
    int wm = wid & 1, wn = wid >> 1;     // mma warp tiling
    int cig = t & 7;                      // sampling: 8-ci group (16B)

    float acc[2][4][4];
#pragma unroll
    for (int i = 0; i < 2; i++)
#pragma unroll
        for (int j = 0; j < 4; j++)
#pragma unroll
            for (int l = 0; l < 4; l++) acc[i][j][l] = 0.f;

    auto item_load = [&](int k, int g, uint4& a, uint4& c, float& wy) {
        int pix = (t >> 3) + g*32;
        float iy = iy_sh[k*128 + pix];
        float y0f = floorf(iy);
        wy = iy - y0f;
        int y0 = (int)y0f;
        int y1 = min(y0 + 1, 255);
        int ix = min(max(w0 + pix + k - 4, 0), 255);
        uint32_t o0 = (((uint32_t)y0 << 8) + (uint32_t)ix) << 7;
        uint32_t o1 = (((uint32_t)y1 << 8) + (uint32_t)ix) << 7;
        a = __ldg((const uint4*)(xhb + o0 + (cig << 4)));
        c = __ldg((const uint4*)(xhb + o1 + (cig << 4)));
    };
    auto item_store = [&](int g, uint32_t bufoff, uint4 a, uint4 c, float wy) {
        int pix = (t >> 3) + g*32;
        uint4 r;
        const uint32_t* ap = (const uint32_t*)&a;
        const uint32_t* cp = (const uint32_t*)&c;
        uint32_t* rp = (uint32_t*)&r;
#pragma unroll
        for (int j = 0; j < 4; j++) {
            __half2 ah, ch;
            memcpy(&ah, ap + j, 4); memcpy(&ch, cp + j, 4);
            float2 fa = __half22float2(ah), fc = __half22float2(ch);
            float2 f;
            f.x = fmaf(fc.x - fa.x, wy, fa.x);
            f.y = fmaf(fc.y - fa.y, wy, fa.y);
            __half2 hr = __floats2half2_rn(f.x, f.y);
            memcpy(rp + j, &hr, 4);
        }
        uint32_t off = (uint32_t)(pix*128 + (cig << 4));
        uint32_t sw = off ^ ((off >> 3) & 0x70);
        *(uint4*)(smem + bufoff + sw) = r;
    };
    auto wcopy = [&](int k, uint32_t bufoff) {
        const char* wsrc = (const char*)g_wh + (size_t)k*8192 + t*32;
        cpasync16(sb + bufoff + t*32,      wsrc);
        cpasync16(sb + bufoff + t*32 + 16, wsrc + 16);
        asm volatile("cp.async.commit_group;" ::: "memory");
    };
    auto mma_kt = [&](int kt, uint32_t soff, uint32_t woff) {
        uint32_t af[2][4];
#pragma unroll
        for (int mt = 0; mt < 2; mt++) {
            uint32_t row = (uint32_t)(wm*32 + mt*16 + (lane & 15));
            uint32_t c16 = (uint32_t)(kt*2 + (lane >> 4));
            uint32_t off = row*128 + c16*16;
            uint32_t sw = off ^ ((off >> 3) & 0x70);
            ldsm_x4(af[mt], sb + woff + sw);
        }
#pragma unroll
        for (int nt = 0; nt < 4; nt++) {
            uint32_t bf[2];
            uint32_t row = (uint32_t)(wn*32 + nt*8 + (lane & 7));
            uint32_t c16 = (uint32_t)(kt*2 + ((lane >> 3) & 1));
            uint32_t off = row*128 + c16*16;
            uint32_t sw = off ^ ((off >> 3) & 0x70);
            ldsm_x2(bf, sb + soff + sw);
            mma16816h(acc[0][nt], af[0], bf);
            mma16816h(acc[1][nt], af[1], bf);
        }
    };

    // prologue
    wcopy(0, OFF_WH(0));
    __syncthreads();
#pragma unroll
    for (int g = 0; g < 4; g++) {
        uint4 a, c; float wy;
        item_load(0, g, a, c, wy);
        item_store(g, OFF_SH(0), a, c, wy);
    }
    asm volatile("cp.async.wait_group 0;" ::: "memory");
    __syncthreads();

#pragma unroll 1
    for (int k = 0; k < KK; k++) {
        int st = k & 1, ns = st ^ 1;
        bool pf = (k < KK-1);
        uint32_t soff = OFF_SH(st), woff = OFF_WH(st);

        uint4 a0, c0; float wy0 = 0.f;
        if (pf) {
            wcopy(k+1, OFF_WH(ns));
            item_load(k+1, 0, a0, c0, wy0);    // chunk 0 in flight
        }

#pragma unroll
        for (int g = 0; g < 4; g++) {
            uint4 a1, c1; float wy1 = 0.f;
            if (pf && g < 3) item_load(k+1, g+1, a1, c1, wy1);   // next chunk in flight
            mma_kt(g, soff, woff);
            if (pf) item_store(g, OFF_SH(ns), a0, c0, wy0);      // data loaded >=1 mma ago
            a0 = a1; c0 = c1; wy0 = wy1;
        }

        if (pf) { asm volatile("cp.async.wait_group 0;" ::: "memory"); }
        __syncthreads();
    }

    // epilogue: bias, store, GN partial sums
    {
        int q = lane >> 2;
        int pp = (lane & 3) * 2;
        float s_l[2][2] = {{0.f,0.f},{0.f,0.f}}, q_l[2][2] = {{0.f,0.f},{0.f,0.f}};
#pragma unroll
        for (int mt = 0; mt < 2; mt++) {
            int cog = wm*32 + mt*16 + q;
            float b0 = __ldg(b_dsc + cog);
            float b1 = __ldg(b_dsc + cog + 8);
#pragma unroll
            for (int nt = 0; nt < 4; nt++) {
                int pix = wn*32 + nt*8 + pp;
                float v0 = acc[mt][nt][0] + b0;
                float v1 = acc[mt][nt][1] + b0;
                float v2 = acc[mt][nt][2] + b1;
                float v3 = acc[mt][nt][3] + b1;
                *(float2*)&out[((size_t)(b*64 + cog)*HH + h)*WW + w0 + pix]     = make_float2(v0, v1);
                *(float2*)&out[((size_t)(b*64 + cog + 8)*HH + h)*WW + w0 + pix] = make_float2(v2, v3);
                s_l[mt][0] += v0 + v1; q_l[mt][0] += v0*v0 + v1*v1;
                s_l[mt][1] += v2 + v3; q_l[mt][1] += v2*v2 + v3*v3;
            }
        }
#pragma unroll
        for (int mt = 0; mt < 2; mt++)
#pragma unroll
            for (int hf = 0; hf < 2; hf++) {
#pragma unroll
                for (int m = 1; m <= 2; m <<= 1) {
                    s_l[mt][hf] += __shfl_xor_sync(0xffffffff, s_l[mt][hf], m);
                    q_l[mt][hf] += __shfl_xor_sync(0xffffffff, q_l[mt][hf], m);
                }
                if ((lane & 3) == 0) {
                    int grp = (wm*32 + mt*16 + hf*8 + q) >> 2;
                    atomicAdd(&sums[2*grp],   s_l[mt][hf]);
                    atomicAdd(&sums[2*grp+1], q_l[mt][hf]);
                }
            }
    }
    __syncthreads();
    if (t < 32) {
        int bw = blockIdx.x + 2*h;
        g_part[((size_t)(b*512 + bw)*16 + (t >> 1))*2 + (t & 1)] = sums[t];
    }
}

// ---------------- kernel 6: reduce out-GN partials ----------------
__global__ void outstats_kernel() {
    int b = blockIdx.x >> 4, g = blockIdx.x & 15;
    int t = threadIdx.x;
    float s = 0.f, q = 0.f;
    for (int i = t; i < 512; i += 256) {
        size_t idx = ((size_t)(b*512 + i)*16 + g)*2;
        s += g_part[idx];
        q += g_part[idx + 1];
    }
    __shared__ float rs[256], rq[256];
    rs[t] = s; rq[t] = q; __syncthreads();
    for (int o = 128; o > 0; o >>= 1) {
        if (t < o) { rs[t] += rs[t+o]; rq[t] += rq[t+o]; }
        __syncthreads();
    }
    if (t == 0) {
        float n = 4.f * HW;
        float mean = rs[0] / n;
        float var = rq[0] / n - mean*mean;
        g_outmr[(b*16+g)*2]   = mean;
        g_outmr[(b*16+g)*2+1] = rsqrtf(var + 1e-5f);
    }
}

// ---------------- kernel 7: apply GN + ReLU ----------------
__global__ void apply_kernel(float* __restrict__ out,
                             const float* __restrict__ gn_w,
                             const float* __restrict__ gn_b) {
    int idx4 = blockIdx.x*blockDim.x + threadIdx.x;
    size_t base = (size_t)idx4 * 4;
    int co = (int)((base >> 16) & 63);
    int b  = (int)(base >> 22);
    int g  = co >> 2;
    float mean = g_outmr[(b*16+g)*2];
    float rstd = g_outmr[(b*16+g)*2+1];
    float sc = rstd * gn_w[co];
    float sh = gn_b[co] - mean * sc;
    float4 v = *(float4*)&out[base];
    v.x = fmaxf(fmaf(v.x, sc, sh), 0.f);
    v.y = fmaxf(fmaf(v.y, sc, sh), 0.f);
    v.z = fmaxf(fmaf(v.z, sc, sh), 0.f);
    v.w = fmaxf(fmaf(v.w, sc, sh), 0.f);
    *(float4*)&out[base] = v;
}

// ---------------- launch ----------------
extern "C" void kernel_launch(void* const* d_in, const int* in_sizes, int n_in,
                              void* d_out, int out_size) {
    const float* x     = (const float*)d_in[0];
    const float* w_off = (const float*)d_in[1];
    const float* b_off = (const float*)d_in[2];
    const float* gno_w = (const float*)d_in[3];
    const float* gno_b = (const float*)d_in[4];
    const float* w_dsc = (const float*)d_in[5];
    const float* b_dsc = (const float*)d_in[6];
    const float* gn_w  = (const float*)d_in[7];
    const float* gn_b  = (const float*)d_in[8];
    float* out = (float*)d_out;

    cudaFuncSetAttribute(main_kernel, cudaFuncAttributeMaxDynamicSharedMemorySize, SMEM_BYTES);
    cudaFuncSetAttribute(conv1g_kernel, cudaFuncAttributeMaxDynamicSharedMemorySize, C1_SMEM);

    xprep_kernel<<<dim3(HH, BN), 256>>>(x);
    wprep_kernel<<<(KK*64*64 + 255)/256, 256>>>(w_dsc);
    wprepc1_kernel<<<(KK*16*64 + 255)/256, 256>>>(w_off);
    conv1g_kernel<<<dim3(2, HH/2, BN), 256, C1_SMEM>>>(b_off);
    offstats_kernel<<<BN*5, 256>>>();
    main_kernel<<<dim3(2, HH, BN), 256, SMEM_BYTES>>>(x, gno_w, gno_b, b_dsc, out);
    outstats_kernel<<<BN*16, 256>>>();
    apply_kernel<<<4096, 512>>>(out, gn_w, gn_b);
}